// round 8
// baseline (speedup 1.0000x reference)
#include <cuda_runtime.h>
#include <cstdint>

#define NTAGS 48
#define SEQ 512
#define BSZ 64
#define NTRANS (NTAGS*NTAGS)          // 2304
#define RST 50                         // exp-tile smem row stride (floats)
#define TILE_PAD (NTAGS*RST)           // 2400 floats = 9600 B
#define NCHAIN 384
#define NTHREADS 768
#define LOG2E_F 1.4426950408889634f
#define LN2_D   0.6931471805599453
#define START_TAG 46
#define END_TAG 47

__device__ float g_part[BSZ];

__device__ __forceinline__ float ex2f(float x){
    float y; asm("ex2.approx.ftz.f32 %0, %1;" : "=f"(y) : "f"(x)); return y;
}
__device__ __forceinline__ float lg2f(float x){
    float y; asm("lg2.approx.ftz.f32 %0, %1;" : "=f"(y) : "f"(x)); return y;
}

__global__ __launch_bounds__(NTHREADS, 1)
void crf_fwd_kernel(const float* __restrict__ tr,
                    const int* __restrict__ tgt)
{
    __shared__ __align__(16) float expbuf[2][TILE_PAD];  // 19200 B, exp(tr) tiles
    __shared__ __align__(16) float vbuf[2][NTAGS];       // normalized exp(forw)
    __shared__ float scalebuf[2];
    __shared__ float tsc_sh;
    __shared__ int   sP0;
    __shared__ unsigned char tg[SEQ];

    const int tid = threadIdx.x;
    const int b   = blockIdx.x;
    const float* trb = tr + (size_t)b * SEQ * NTRANS;

    // ---- targets + zero accumulators ----
    if (tid < SEQ){
        int v = tgt[(size_t)b * SEQ + tid];
        tg[tid] = (unsigned char)(((unsigned)v < NTAGS) ? v : 0);
    }
    if (tid == 0) tsc_sh = 0.f;
    __syncthreads();

    // ---- target_score: all gather addresses known upfront; one element/thread ----
    {
        float acc = 0.f;
        if (tid < SEQ){
            int pr = (tid == 0) ? START_TAG : (int)tg[tid-1];
            int cu = (int)tg[tid];
            acc = __ldg(trb + (size_t)tid * NTRANS + pr * NTAGS + cu);
        }
        #pragma unroll
        for (int m = 16; m > 0; m >>= 1) acc += __shfl_xor_sync(0xffffffffu, acc, m);
        if ((tid & 31) == 0) atomicAdd(&tsc_sh, acc);
    }

    // ---- role setup ----
    const bool is_chain = (tid < NCHAIN);
    const int  w   = tid >> 5;
    const int  l   = tid & 31;
    const int  col = ((w & 15) << 2) + (l & 3);   // chain: column 0..47
    const int  q   = l >> 2;                      // chain: rows 6q..6q+5
    const int  r0  = q * 6;

    const int  e   = tid - NCHAIN;                // exp thread id 0..383
    const int  er  = (e >= 0) ? (e / NTAGS) : 0;  // exp: base row 0..7
    const int  ec  = (e >= 0) ? (e % NTAGS) : 0;  // exp: column
    const int  sbo = er * RST + ec;               // exp STS base (stride 8*RST per k)

    // ---- prologue loads ----
    float f0v = 0.f;                // chain tid<48: forw0 element
    float tA[6], tB[6], t1[6];      // exp raw regs
    if (is_chain){
        if (tid < NTAGS) f0v = __ldg(trb + START_TAG * NTAGS + tid);
        if (tid == 0)    sP0 = __float2int_rn(__ldg(trb + START_TAG * NTAGS) * LOG2E_F);
    } else {
        const float* g1 = trb + 1 * NTRANS;
        const float* g2 = trb + 2 * NTRANS;
        const float* g3 = trb + 3 * NTRANS;
        #pragma unroll
        for (int k = 0; k < 6; ++k){
            t1[k] = __ldg(g1 + e + 384*k);
            tA[k] = __ldg(g2 + e + 384*k);
            tB[k] = __ldg(g3 + e + 384*k);
        }
    }
    __syncthreads();                // sP0 + tscore atomics published

    // ---- init v0, exp(tile1) ----
    if (is_chain){
        if (tid < NTAGS)
            vbuf[0][tid] = ex2f(fmaf(f0v, LOG2E_F, (float)(-sP0)));
    } else {
        #pragma unroll
        for (int k = 0; k < 6; ++k)
            expbuf[1][sbo + k * 8 * RST] = ex2f(t1[k] * LOG2E_F);
    }
    __syncthreads();                // vbuf[0] + expbuf[1] published

    int Ksum = 0, kcur = 0;         // exp thread 0 (tid 384)
    if (tid == NCHAIN){
        int eb = (__float_as_int(vbuf[0][0]) >> 23) & 255;
        kcur = eb - 127;
        scalebuf[1] = __int_as_float((127 - kcur) << 23);
    }

    // ---- main loop ----
    for (int t = 1; t < SEQ; ++t){
        __syncthreads();            // publishes: expbuf[t&1], vbuf[(t-1)&1], scalebuf[t&1]

        if (is_chain){
            // pure recurrence: nothing else in these warps' instruction stream
            const float  sc  = scalebuf[t & 1];
            const float* E   = &expbuf[t & 1][0];
            const float2* vp2 = (const float2*)&vbuf[(t-1) & 1][0];
            float2 va = vp2[3*q], vb = vp2[3*q+1], vc = vp2[3*q+2];
            float e0 = E[(r0  )*RST + col], e1 = E[(r0+1)*RST + col];
            float e2 = E[(r0+2)*RST + col], e3 = E[(r0+3)*RST + col];
            float e4 = E[(r0+4)*RST + col], e5 = E[(r0+5)*RST + col];
            float s01 = fmaf(e1, va.y, e0 * va.x);
            float s23 = fmaf(e3, vb.y, e2 * vb.x);
            float s45 = fmaf(e5, vc.y, e4 * vc.x);
            float s = (s01 + s23) + s45;
            s += __shfl_xor_sync(0xffffffffu, s, 4);
            s += __shfl_xor_sync(0xffffffffu, s, 8);
            s += __shfl_xor_sync(0xffffffffu, s, 16);
            float v = s * sc;
            if (q == 0) vbuf[t & 1][col] = v;
        } else {
            // convert tile t+1 (regs) -> expbuf[(t+1)&1]; refill regs with tile t+3
            if (t + 1 < SEQ){
                float* dst = &expbuf[(t+1) & 1][0];
                if (t & 1){
                    #pragma unroll
                    for (int k = 0; k < 6; ++k)
                        dst[sbo + k * 8 * RST] = ex2f(tA[k] * LOG2E_F);
                    if (t + 3 < SEQ){
                        const float* g = trb + (size_t)(t+3) * NTRANS;
                        #pragma unroll
                        for (int k = 0; k < 6; ++k) tA[k] = __ldg(g + e + 384*k);
                    }
                } else {
                    #pragma unroll
                    for (int k = 0; k < 6; ++k)
                        dst[sbo + k * 8 * RST] = ex2f(tB[k] * LOG2E_F);
                    if (t + 3 < SEQ){
                        const float* g = trb + (size_t)(t+3) * NTRANS;
                        #pragma unroll
                        for (int k = 0; k < 6; ++k) tB[k] = __ldg(g + e + 384*k);
                    }
                }
            }
            if (tid == NCHAIN){
                Ksum += kcur;                       // scale applied at step t
                float w0 = vbuf[(t-1) & 1][0];      // 2-step-stale source for k_{t+1}
                int eb = (__float_as_int(w0) >> 23) & 255;
                kcur = eb - 127;
                scalebuf[(t+1) & 1] = __int_as_float((127 - kcur) << 23);
            }
        }
    }

    __syncthreads();
    if (tid == NCHAIN){
        float vf = vbuf[(SEQ-1) & 1][END_TAG];
        int   eu = ((__float_as_int(vf) >> 23) & 255) - 127;
        float mu = __int_as_float((__float_as_int(vf) & 0x807FFFFF) | 0x3F800000);
        double log2u = (double)(eu + sP0 + Ksum) + (double)lg2f(mu);
        g_part[b] = (float)(LN2_D * log2u - (double)tsc_sh);
    }
}

__global__ void finalize_kernel(float* o){
    int t = threadIdx.x;                      // 32 threads
    double v = (double)g_part[t] + (double)g_part[t + 32];
    #pragma unroll
    for (int m = 16; m > 0; m >>= 1)
        v += __shfl_xor_sync(0xffffffffu, v, m);
    if (t == 0) *o = (float)(v * (1.0 / (double)BSZ));
}

extern "C" void kernel_launch(void* const* d_in, const int* in_sizes, int n_in,
                              void* d_out, int out_size)
{
    const float* tr  = (const float*)d_in[0];
    const int*   tgt = (const int*)d_in[1];
    float*       out = (float*)d_out;

    crf_fwd_kernel<<<BSZ, NTHREADS>>>(tr, tgt);
    finalize_kernel<<<1, 32>>>(out);
}

// round 9
// speedup vs baseline: 1.8185x; 1.8185x over previous
#include <cuda_runtime.h>
#include <cstdint>

#define NTAGS 48
#define SEQ 512
#define BSZ 64
#define NTRANS (NTAGS*NTAGS)          // 2304
#define RST 50                         // exp-tile smem row stride (floats)
#define TILE_PAD (NTAGS*RST)           // 2400 floats = 9600 B
#define NCHAIN 384
#define NTHREADS 768
#define LOG2E_F 1.4426950408889634f
#define LN2_D   0.6931471805599453
#define START_TAG 46
#define END_TAG 47

__device__ float g_part[BSZ];

__device__ __forceinline__ float ex2f(float x){
    float y; asm("ex2.approx.ftz.f32 %0, %1;" : "=f"(y) : "f"(x)); return y;
}
__device__ __forceinline__ float lg2f(float x){
    float y; asm("lg2.approx.ftz.f32 %0, %1;" : "=f"(y) : "f"(x)); return y;
}

__global__ __launch_bounds__(NTHREADS, 1)
void crf_fwd_kernel(const float* __restrict__ tr,
                    const int* __restrict__ tgt)
{
    __shared__ __align__(16) float expbuf[2][TILE_PAD];  // 19200 B, exp(tr) tiles
    __shared__ __align__(16) float vbuf[2][NTAGS];       // normalized exp(forw)
    __shared__ float scalebuf[2];
    __shared__ float tsc_sh;
    __shared__ int   sP0;
    __shared__ unsigned char tg[SEQ];

    const int tid = threadIdx.x;
    const int b   = blockIdx.x;
    const float* trb = tr + (size_t)b * SEQ * NTRANS;

    // ---- targets ----
    if (tid < SEQ){
        int v = tgt[(size_t)b * SEQ + tid];
        tg[tid] = (unsigned char)(((unsigned)v < NTAGS) ? v : 0);
    }
    if (tid == 0) tsc_sh = 0.f;
    __syncthreads();

    // ---- target_score: one gathered element per thread, reduce in prologue ----
    {
        float acc = 0.f;
        if (tid < SEQ){
            int pr = (tid == 0) ? START_TAG : (int)tg[tid-1];
            int cu = (int)tg[tid];
            acc = __ldg(trb + (size_t)tid * NTRANS + pr * NTAGS + cu);
        }
        #pragma unroll
        for (int m = 16; m > 0; m >>= 1) acc += __shfl_xor_sync(0xffffffffu, acc, m);
        if ((tid & 31) == 0) atomicAdd(&tsc_sh, acc);
    }

    // ---- role setup ----
    const bool is_chain = (tid < NCHAIN);
    const int  w   = tid >> 5;
    const int  l   = tid & 31;
    const int  col = ((w & 15) << 2) + (l & 3);   // chain: column 0..47
    const int  q   = l >> 2;                      // chain: rows 6q..6q+5
    const int  r0  = q * 6;

    const int  e   = tid - NCHAIN;                // exp thread id 0..383
    const int  er  = (e >= 0) ? (e / NTAGS) : 0;
    const int  ec  = (e >= 0) ? (e % NTAGS) : 0;
    const int  sbo = er * RST + ec;               // exp STS base; row stride 8*RST per k

    // ---- prologue loads ----
    float f0v = 0.f;
    float t1[6];                      // raw tile 1
    float tb0[6], tb1[6], tb2[6], tb3[6];  // 4-deep raw-tile register pipeline
    if (is_chain){
        if (tid < NTAGS) f0v = __ldg(trb + START_TAG * NTAGS + tid);
        if (tid == 0)    sP0 = __float2int_rn(__ldg(trb + START_TAG * NTAGS) * LOG2E_F);
    } else {
        #pragma unroll
        for (int k = 0; k < 6; ++k){
            t1[k]  = __ldg(trb + 1 * NTRANS + e + 384*k);
            tb2[k] = __ldg(trb + 2 * NTRANS + e + 384*k);  // tile 2 -> buf (2&3)=2
            tb3[k] = __ldg(trb + 3 * NTRANS + e + 384*k);  // tile 3
            tb0[k] = __ldg(trb + 4 * NTRANS + e + 384*k);  // tile 4 -> buf 0
            tb1[k] = __ldg(trb + 5 * NTRANS + e + 384*k);  // tile 5 -> buf 1
        }
    }
    __syncthreads();                 // sP0 + tscore published

    // ---- init v0 and exp(tile 1) ----
    if (is_chain){
        if (tid < NTAGS)
            vbuf[0][tid] = ex2f(fmaf(f0v, LOG2E_F, (float)(-sP0)));
    } else {
        #pragma unroll
        for (int k = 0; k < 6; ++k)
            expbuf[1][sbo + k * 8 * RST] = ex2f(t1[k] * LOG2E_F);
    }
    __syncthreads();                 // vbuf[0] + expbuf[1] published

    int Ksum = 0, kcur = 0;          // tid NCHAIN only
    if (tid == NCHAIN){
        int eb = (__float_as_int(vbuf[0][0]) >> 23) & 255;
        kcur = eb - 127;
        scalebuf[1] = __int_as_float((127 - kcur) << 23);
    }

#define DO_STEP(T, TB) do {                                                     \
    __syncthreads();                                                            \
    if (is_chain){                                                              \
        const float  sc  = scalebuf[(T) & 1];                                   \
        const float* E   = &expbuf[(T) & 1][0];                                 \
        const float2* vp2 = (const float2*)&vbuf[((T)-1) & 1][0];               \
        float2 va = vp2[3*q], vb = vp2[3*q+1], vc = vp2[3*q+2];                 \
        float e0 = E[(r0  )*RST + col], e1 = E[(r0+1)*RST + col];               \
        float e2 = E[(r0+2)*RST + col], e3 = E[(r0+3)*RST + col];               \
        float e4 = E[(r0+4)*RST + col], e5 = E[(r0+5)*RST + col];               \
        float s01 = fmaf(e1, va.y, e0 * va.x);                                  \
        float s23 = fmaf(e3, vb.y, e2 * vb.x);                                  \
        float s45 = fmaf(e5, vc.y, e4 * vc.x);                                  \
        float s = (s01 + s23) + s45;                                            \
        s += __shfl_xor_sync(0xffffffffu, s, 4);                                \
        s += __shfl_xor_sync(0xffffffffu, s, 8);                                \
        s += __shfl_xor_sync(0xffffffffu, s, 16);                               \
        float v = s * sc;                                                       \
        if (q == 0) vbuf[(T) & 1][col] = v;                                     \
    } else {                                                                    \
        if ((T) + 1 < SEQ){                                                     \
            float* dst = &expbuf[((T)+1) & 1][0];                               \
            dst[sbo + 0*8*RST] = ex2f(TB[0] * LOG2E_F);                         \
            dst[sbo + 1*8*RST] = ex2f(TB[1] * LOG2E_F);                         \
            dst[sbo + 2*8*RST] = ex2f(TB[2] * LOG2E_F);                         \
            dst[sbo + 3*8*RST] = ex2f(TB[3] * LOG2E_F);                         \
            dst[sbo + 4*8*RST] = ex2f(TB[4] * LOG2E_F);                         \
            dst[sbo + 5*8*RST] = ex2f(TB[5] * LOG2E_F);                         \
        }                                                                       \
        if ((T) + 5 < SEQ){                                                     \
            const float* g = trb + (size_t)((T)+5) * NTRANS;                    \
            TB[0] = __ldg(g + e        ); TB[1] = __ldg(g + e +  384);          \
            TB[2] = __ldg(g + e +  768); TB[3] = __ldg(g + e + 1152);           \
            TB[4] = __ldg(g + e + 1536); TB[5] = __ldg(g + e + 1920);           \
        }                                                                       \
        if (tid == NCHAIN){                                                     \
            Ksum += kcur;                                                       \
            float w0 = vbuf[((T)-1) & 1][0];                                    \
            int eb = (__float_as_int(w0) >> 23) & 255;                          \
            kcur = eb - 127;                                                    \
            scalebuf[((T)+1) & 1] = __int_as_float((127 - kcur) << 23);         \
        }                                                                       \
    }                                                                           \
} while(0)

    // main loop: t = 1..508 in blocks of 4 (buffer = (t+1) & 3, compile-time)
    for (int t = 1; t + 3 < SEQ; t += 4){
        DO_STEP(t    , tb2);
        DO_STEP(t + 1, tb3);
        DO_STEP(t + 2, tb0);
        DO_STEP(t + 3, tb1);
    }
    // tail: t = 509, 510, 511
    DO_STEP(509, tb2);
    DO_STEP(510, tb3);
    DO_STEP(511, tb0);
#undef DO_STEP

    __syncthreads();
    if (tid == NCHAIN){
        float vf = vbuf[(SEQ-1) & 1][END_TAG];
        int   eu = ((__float_as_int(vf) >> 23) & 255) - 127;
        float mu = __int_as_float((__float_as_int(vf) & 0x807FFFFF) | 0x3F800000);
        double log2u = (double)(eu + sP0 + Ksum) + (double)lg2f(mu);
        g_part[b] = (float)(LN2_D * log2u - (double)tsc_sh);
    }
}

__global__ void finalize_kernel(float* o){
    int t = threadIdx.x;                      // 32 threads
    double v = (double)g_part[t] + (double)g_part[t + 32];
    #pragma unroll
    for (int m = 16; m > 0; m >>= 1)
        v += __shfl_xor_sync(0xffffffffu, v, m);
    if (t == 0) *o = (float)(v * (1.0 / (double)BSZ));
}

extern "C" void kernel_launch(void* const* d_in, const int* in_sizes, int n_in,
                              void* d_out, int out_size)
{
    const float* tr  = (const float*)d_in[0];
    const int*   tgt = (const int*)d_in[1];
    float*       out = (float*)d_out;

    crf_fwd_kernel<<<BSZ, NTHREADS>>>(tr, tgt);
    finalize_kernel<<<1, 32>>>(out);
}

// round 10
// speedup vs baseline: 2.3112x; 1.2709x over previous
#include <cuda_runtime.h>
#include <cstdint>

#define NTAGS 48
#define SEQ 512
#define BSZ 64
#define NTRANS (NTAGS*NTAGS)          // 2304
#define RST 50                         // smem row stride (floats)
#define TILE_PAD (NTAGS*RST)           // 2400 floats = 9600 B
#define STAGES 5
#define NTHREADS 384
#define LOG2E_F 1.4426950408889634f
#define LN2_D   0.6931471805599453
#define START_TAG 46
#define END_TAG 47

__device__ float g_part[BSZ];
__device__ unsigned int g_done = 0;

__device__ __forceinline__ float ex2f(float x){
    float y; asm("ex2.approx.ftz.f32 %0, %1;" : "=f"(y) : "f"(x)); return y;
}
__device__ __forceinline__ float lg2f(float x){
    float y; asm("lg2.approx.ftz.f32 %0, %1;" : "=f"(y) : "f"(x)); return y;
}
__device__ __forceinline__ void cp8(uint32_t s, const void* g){
    asm volatile("cp.async.ca.shared.global [%0], [%1], 8;" :: "r"(s), "l"(g));
}
__device__ __forceinline__ void cp_commit(){ asm volatile("cp.async.commit_group;"); }
__device__ __forceinline__ void cp_wait2(){ asm volatile("cp.async.wait_group 2;"); }
__device__ __forceinline__ void cp_wait3(){ asm volatile("cp.async.wait_group 3;"); }

__global__ __launch_bounds__(NTHREADS, 1)
void crf_fwd_kernel(const float* __restrict__ tr,
                    const int* __restrict__ tgt,
                    float* __restrict__ out)
{
    __shared__ __align__(16) float buf[STAGES][TILE_PAD];  // 48000 B
    __shared__ __align__(16) float vbuf[2][NTAGS];
    __shared__ float scalebuf[2];
    __shared__ float tsc_sh;
    __shared__ unsigned int rank_sh;
    __shared__ unsigned char tg[SEQ];

    const int tid = threadIdx.x;
    const int b   = blockIdx.x;
    const float* trb = tr + (size_t)b * SEQ * NTRANS;

    // ---- targets ----
    if (tid < SEQ){
        int v = tgt[(size_t)b * SEQ + tid];
        tg[tid] = (unsigned char)(((unsigned)v < NTAGS) ? v : 0);
    }
    if (tid == 0) tsc_sh = 0.f;
    __syncthreads();

    // ---- target_score: all 512 gathers in the prologue, off the recurrence ----
    {
        float acc = 0.f;
        if (tid < SEQ){
            int pr = (tid == 0) ? START_TAG : (int)tg[tid-1];
            int cu = (int)tg[tid];
            acc = __ldg(trb + (size_t)tid * NTRANS + pr * NTAGS + cu);
        }
        #pragma unroll
        for (int m = 16; m > 0; m >>= 1) acc += __shfl_xor_sync(0xffffffffu, acc, m);
        if ((tid & 31) == 0) atomicAdd(&tsc_sh, acc);
    }

    const int w   = tid >> 5;
    const int l   = tid & 31;
    const int col = (w << 2) + (l & 3);   // column 0..47
    const int q   = l >> 2;               // rows 6q..6q+5
    const int r0  = q * 6;

    // 8B cp.async chunk coords (3 chunks/thread, 1152 per tile)
    const int cA = tid, cB = tid + NTHREADS, cC = tid + 2*NTHREADS;
    const uint32_t smA = (uint32_t)((cA/24)*(RST*4) + (cA%24)*8);
    const uint32_t smB = (uint32_t)((cB/24)*(RST*4) + (cB%24)*8);
    const uint32_t smC = (uint32_t)((cC/24)*(RST*4) + (cC%24)*8);
    const int gmA = (cA/24)*NTAGS + (cA%24)*2;
    const int gmB = (cB/24)*NTAGS + (cB%24)*2;
    const int gmC = (cC/24)*NTAGS + (cC%24)*2;
    const uint32_t sbase = (uint32_t)__cvta_generic_to_shared(&buf[0][0]);

    auto prefetch = [&](int tile_idx, int stg){
        uint32_t sb = sbase + (uint32_t)stg * (TILE_PAD*4);
        const float* gb = trb + (size_t)tile_idx * NTRANS;
        cp8(sb + smA, gb + gmA);
        cp8(sb + smB, gb + gmB);
        cp8(sb + smC, gb + gmC);
    };

    prefetch(0,0); cp_commit();
    prefetch(1,1); cp_commit();
    prefetch(2,2); cp_commit();
    prefetch(3,3); cp_commit();
    prefetch(4,4); cp_commit();

    cp_wait3();            // tiles 0,1 complete
    __syncthreads();

    // ---- init (t = 0) ----
    const float* b0 = &buf[0][0];
    const int P0 = __float2int_rn(b0[START_TAG*RST] * LOG2E_F);
    float v0 = ex2f(fmaf(b0[START_TAG*RST + col], LOG2E_F, (float)(-P0)));
    if (q == 0) vbuf[0][col] = v0;

    int Ksum = 0, kcur = 0;   // tid 4 only
    if (tid == 4){
        int e = (__float_as_int(v0) >> 23) & 255;   // v0 here is col 0
        kcur = e - 127;
        scalebuf[1] = __int_as_float((127 - kcur) << 23);
    }

    // Etr for step 1 from tile 1
    float E0,E1,E2,E3,E4,E5;
    {
        const float* tn = &buf[1][0];
        E0 = ex2f(tn[(r0  )*RST + col] * LOG2E_F);
        E1 = ex2f(tn[(r0+1)*RST + col] * LOG2E_F);
        E2 = ex2f(tn[(r0+2)*RST + col] * LOG2E_F);
        E3 = ex2f(tn[(r0+3)*RST + col] * LOG2E_F);
        E4 = ex2f(tn[(r0+4)*RST + col] * LOG2E_F);
        E5 = ex2f(tn[(r0+5)*RST + col] * LOG2E_F);
    }

    int st = 1;                                  // stage holding tile t
    for (int t = 1; t < SEQ; ++t){
        cp_wait2();        // tiles <= t+1 complete
        __syncthreads();   // vbuf/scalebuf of t-1 visible; stage (t-1)%5 free

        const int stp = (st == 0) ? 4 : st - 1;
        const int stn = (st == 4) ? 0 : st + 1;
        if (t + 4 < SEQ) prefetch(t + 4, stp);
        cp_commit();       // uniform group count

        const float  sc = scalebuf[t & 1];
        const float* vp = &vbuf[(t-1) & 1][0];
        const float2* vp2 = (const float2*)vp;
        float2 va = vp2[3*q], vb = vp2[3*q+1], vc = vp2[3*q+2];

        // off-path: Etr for step t+1 from tile t+1 (stale data at t=SEQ-1, unused)
        float F0,F1,F2,F3,F4,F5;
        {
            const float* tn = &buf[stn][0];
            F0 = ex2f(tn[(r0  )*RST + col] * LOG2E_F);
            F1 = ex2f(tn[(r0+1)*RST + col] * LOG2E_F);
            F2 = ex2f(tn[(r0+2)*RST + col] * LOG2E_F);
            F3 = ex2f(tn[(r0+3)*RST + col] * LOG2E_F);
            F4 = ex2f(tn[(r0+4)*RST + col] * LOG2E_F);
            F5 = ex2f(tn[(r0+5)*RST + col] * LOG2E_F);
        }

        // critical chain (E regs from previous iter)
        float s01 = fmaf(E1, va.y, E0 * va.x);
        float s23 = fmaf(E3, vb.y, E2 * vb.x);
        float s45 = fmaf(E5, vc.y, E4 * vc.x);
        float s = (s01 + s23) + s45;
        s += __shfl_xor_sync(0xffffffffu, s, 4);
        s += __shfl_xor_sync(0xffffffffu, s, 8);
        s += __shfl_xor_sync(0xffffffffu, s, 16);
        float v = s * sc;
        if (q == 0) vbuf[t & 1][col] = v;

        if (tid == 4){
            Ksum += kcur;
            float w0 = vp[0];                     // 2-step-stale scale source
            int e = (__float_as_int(w0) >> 23) & 255;
            kcur = e - 127;
            scalebuf[(t+1) & 1] = __int_as_float((127 - e + 127) << 23);
        }

        E0=F0; E1=F1; E2=F2; E3=F3; E4=F4; E5=F5;
        st = stn;
    }

    __syncthreads();
    // ---- per-block result + threadfence reduction (single-kernel finalize) ----
    if (tid == 4){
        float vf = vbuf[(SEQ-1) & 1][END_TAG];
        int   eu = ((__float_as_int(vf) >> 23) & 255) - 127;
        float mu = __int_as_float((__float_as_int(vf) & 0x807FFFFF) | 0x3F800000);
        double log2u = (double)(eu + P0 + Ksum) + (double)lg2f(mu);
        g_part[b] = (float)(LN2_D * log2u - (double)tsc_sh);
        __threadfence();
        rank_sh = atomicAdd(&g_done, 1u);
    }
    __syncthreads();

    if (rank_sh == BSZ - 1){                      // last block finalizes
        if (tid < 32){
            double vs = (double)__ldcg(&g_part[tid]) + (double)__ldcg(&g_part[tid + 32]);
            #pragma unroll
            for (int m = 16; m > 0; m >>= 1)
                vs += __shfl_xor_sync(0xffffffffu, vs, m);
            if (tid == 0){
                out[0] = (float)(vs * (1.0 / (double)BSZ));
                atomicExch(&g_done, 0u);          // reset for next graph replay
            }
        }
    }
}

extern "C" void kernel_launch(void* const* d_in, const int* in_sizes, int n_in,
                              void* d_out, int out_size)
{
    const float* tr  = (const float*)d_in[0];
    const int*   tgt = (const int*)d_in[1];
    float*       out = (float*)d_out;

    crf_fwd_kernel<<<BSZ, NTHREADS>>>(tr, tgt, out);
}

// round 11
// speedup vs baseline: 2.3260x; 1.0064x over previous
#include <cuda_runtime.h>
#include <cstdint>

#define NTAGS 48
#define SEQ 512
#define BSZ 64
#define NTRANS (NTAGS*NTAGS)          // 2304
#define RST 50                         // smem row stride (floats)
#define TILE_PAD (NTAGS*RST)           // 2400 floats = 9600 B
#define STAGES 5
#define NTHREADS 384
#define LOG2E_F 1.4426950408889634f
#define LN2_D   0.6931471805599453
#define START_TAG 46
#define END_TAG 47

__device__ float g_part[BSZ];
__device__ unsigned int g_done = 0;

__device__ __forceinline__ float ex2f(float x){
    float y; asm("ex2.approx.ftz.f32 %0, %1;" : "=f"(y) : "f"(x)); return y;
}
__device__ __forceinline__ float lg2f(float x){
    float y; asm("lg2.approx.ftz.f32 %0, %1;" : "=f"(y) : "f"(x)); return y;
}
__device__ __forceinline__ void cp8(uint32_t s, const void* g){
    asm volatile("cp.async.ca.shared.global [%0], [%1], 8;" :: "r"(s), "l"(g));
}
__device__ __forceinline__ void cp_commit(){ asm volatile("cp.async.commit_group;"); }
__device__ __forceinline__ void cp_wait2(){ asm volatile("cp.async.wait_group 2;"); }
__device__ __forceinline__ void cp_wait3(){ asm volatile("cp.async.wait_group 3;"); }

__global__ __launch_bounds__(NTHREADS, 1)
void crf_fwd_kernel(const float* __restrict__ tr,
                    const int* __restrict__ tgt,
                    float* __restrict__ out)
{
    __shared__ __align__(16) float buf[STAGES][TILE_PAD];  // 48000 B
    __shared__ __align__(16) float vbuf[2][NTAGS];
    __shared__ float scalebuf[2];
    __shared__ float tsc_sh;
    __shared__ unsigned int rank_sh;
    __shared__ unsigned char tg[SEQ];

    const int tid = threadIdx.x;
    const int b   = blockIdx.x;
    const float* trb = tr + (size_t)b * SEQ * NTRANS;

    // ---- targets ----
    if (tid < SEQ){
        int v = tgt[(size_t)b * SEQ + tid];
        tg[tid] = (unsigned char)(((unsigned)v < NTAGS) ? v : 0);
    }
    if (tid == 0) tsc_sh = 0.f;
    __syncthreads();

    // ---- target_score: all 512 gathers in the prologue, off the recurrence ----
    {
        float acc = 0.f;
        if (tid < SEQ){
            int pr = (tid == 0) ? START_TAG : (int)tg[tid-1];
            int cu = (int)tg[tid];
            acc = __ldg(trb + (size_t)tid * NTRANS + pr * NTAGS + cu);
        }
        #pragma unroll
        for (int m = 16; m > 0; m >>= 1) acc += __shfl_xor_sync(0xffffffffu, acc, m);
        if ((tid & 31) == 0) atomicAdd(&tsc_sh, acc);
    }

    const int w   = tid >> 5;
    const int l   = tid & 31;
    const int col = (w << 2) + (l & 3);   // column 0..47
    const int q   = l >> 2;               // rows 6q..6q+5
    const int r0  = q * 6;

    // 8B cp.async chunk coords (3 chunks/thread, 1152 per tile)
    const int cA = tid, cB = tid + NTHREADS, cC = tid + 2*NTHREADS;
    const uint32_t smA = (uint32_t)((cA/24)*(RST*4) + (cA%24)*8);
    const uint32_t smB = (uint32_t)((cB/24)*(RST*4) + (cB%24)*8);
    const uint32_t smC = (uint32_t)((cC/24)*(RST*4) + (cC%24)*8);
    const int gmA = (cA/24)*NTAGS + (cA%24)*2;
    const int gmB = (cB/24)*NTAGS + (cB%24)*2;
    const int gmC = (cC/24)*NTAGS + (cC%24)*2;
    const uint32_t sbase = (uint32_t)__cvta_generic_to_shared(&buf[0][0]);

    auto prefetch = [&](int tile_idx, int stg){
        uint32_t sb = sbase + (uint32_t)stg * (TILE_PAD*4);
        const float* gb = trb + (size_t)tile_idx * NTRANS;
        cp8(sb + smA, gb + gmA);
        cp8(sb + smB, gb + gmB);
        cp8(sb + smC, gb + gmC);
    };

    prefetch(0,0); cp_commit();
    prefetch(1,1); cp_commit();
    prefetch(2,2); cp_commit();
    prefetch(3,3); cp_commit();
    prefetch(4,4); cp_commit();

    cp_wait3();            // tiles 0,1 complete
    __syncthreads();

    // ---- init (t = 0) ----
    const float* b0 = &buf[0][0];
    const int P0 = __float2int_rn(b0[START_TAG*RST] * LOG2E_F);
    float v0 = ex2f(fmaf(b0[START_TAG*RST + col], LOG2E_F, (float)(-P0)));
    if (q == 0) vbuf[0][col] = v0;

    int Ksum = 0, kcur = 0;   // tid 4 only
    if (tid == 4){
        int e = (__float_as_int(v0) >> 23) & 255;   // v0 here is col 0
        kcur = e - 127;
        scalebuf[1] = __int_as_float((127 - kcur) << 23);
    }

    // Etr for step 1 from tile 1
    float E0,E1,E2,E3,E4,E5;
    {
        const float* tn = &buf[1][0];
        E0 = ex2f(tn[(r0  )*RST + col] * LOG2E_F);
        E1 = ex2f(tn[(r0+1)*RST + col] * LOG2E_F);
        E2 = ex2f(tn[(r0+2)*RST + col] * LOG2E_F);
        E3 = ex2f(tn[(r0+3)*RST + col] * LOG2E_F);
        E4 = ex2f(tn[(r0+4)*RST + col] * LOG2E_F);
        E5 = ex2f(tn[(r0+5)*RST + col] * LOG2E_F);
    }

    int st = 1;                                  // stage holding tile t
    for (int t = 1; t < SEQ; ++t){
        cp_wait2();        // tiles <= t+1 complete
        __syncthreads();   // vbuf/scalebuf of t-1 visible; stage (t-1)%5 free

        const int stp = (st == 0) ? 4 : st - 1;
        const int stn = (st == 4) ? 0 : st + 1;
        if (t + 4 < SEQ) prefetch(t + 4, stp);
        cp_commit();       // uniform group count

        const float  sc = scalebuf[t & 1];
        const float* vp = &vbuf[(t-1) & 1][0];
        const float2* vp2 = (const float2*)vp;
        float2 va = vp2[3*q], vb = vp2[3*q+1], vc = vp2[3*q+2];

        // off-path: Etr for step t+1 from tile t+1 (stale data at t=SEQ-1, unused)
        float F0,F1,F2,F3,F4,F5;
        {
            const float* tn = &buf[stn][0];
            F0 = ex2f(tn[(r0  )*RST + col] * LOG2E_F);
            F1 = ex2f(tn[(r0+1)*RST + col] * LOG2E_F);
            F2 = ex2f(tn[(r0+2)*RST + col] * LOG2E_F);
            F3 = ex2f(tn[(r0+3)*RST + col] * LOG2E_F);
            F4 = ex2f(tn[(r0+4)*RST + col] * LOG2E_F);
            F5 = ex2f(tn[(r0+5)*RST + col] * LOG2E_F);
        }

        // critical chain (E regs from previous iter)
        float s01 = fmaf(E1, va.y, E0 * va.x);
        float s23 = fmaf(E3, vb.y, E2 * vb.x);
        float s45 = fmaf(E5, vc.y, E4 * vc.x);
        float s = (s01 + s23) + s45;
        s += __shfl_xor_sync(0xffffffffu, s, 4);
        s += __shfl_xor_sync(0xffffffffu, s, 8);
        s += __shfl_xor_sync(0xffffffffu, s, 16);
        float v = s * sc;
        if (q == 0) vbuf[t & 1][col] = v;

        if (tid == 4){
            Ksum += kcur;
            float w0 = vp[0];                     // 2-step-stale scale source
            int e = (__float_as_int(w0) >> 23) & 255;
            kcur = e - 127;
            scalebuf[(t+1) & 1] = __int_as_float((127 - e + 127) << 23);
        }

        E0=F0; E1=F1; E2=F2; E3=F3; E4=F4; E5=F5;
        st = stn;
    }

    __syncthreads();
    // ---- per-block result + threadfence reduction (single-kernel finalize) ----
    if (tid == 4){
        float vf = vbuf[(SEQ-1) & 1][END_TAG];
        int   eu = ((__float_as_int(vf) >> 23) & 255) - 127;
        float mu = __int_as_float((__float_as_int(vf) & 0x807FFFFF) | 0x3F800000);
        double log2u = (double)(eu + P0 + Ksum) + (double)lg2f(mu);
        g_part[b] = (float)(LN2_D * log2u - (double)tsc_sh);
        __threadfence();
        rank_sh = atomicAdd(&g_done, 1u);
    }
    __syncthreads();

    if (rank_sh == BSZ - 1){                      // last block finalizes
        if (tid < 32){
            double vs = (double)__ldcg(&g_part[tid]) + (double)__ldcg(&g_part[tid + 32]);
            #pragma unroll
            for (int m = 16; m > 0; m >>= 1)
                vs += __shfl_xor_sync(0xffffffffu, vs, m);
            if (tid == 0){
                out[0] = (float)(vs * (1.0 / (double)BSZ));
                atomicExch(&g_done, 0u);          // reset for next graph replay
            }
        }
    }
}

extern "C" void kernel_launch(void* const* d_in, const int* in_sizes, int n_in,
                              void* d_out, int out_size)
{
    const float* tr  = (const float*)d_in[0];
    const int*   tgt = (const int*)d_in[1];
    float*       out = (float*)d_out;

    crf_fwd_kernel<<<BSZ, NTHREADS>>>(tr, tgt, out);
}

// round 12
// speedup vs baseline: 2.3359x; 1.0042x over previous
#include <cuda_runtime.h>
#include <cstdint>

#define NTAGS 48
#define SEQ 512
#define BSZ 64
#define NTRANS (NTAGS*NTAGS)          // 2304
#define RST 50                         // smem row stride (floats)
#define TILE_PAD (NTAGS*RST)           // 2400 floats = 9600 B
#define STAGES 5
#define NTHREADS 384
#define LOG2E_F 1.4426950408889634f
#define LN2_D   0.6931471805599453
#define START_TAG 46
#define END_TAG 47

__device__ float g_part[BSZ];
__device__ unsigned int g_done = 0;

__device__ __forceinline__ float ex2f(float x){
    float y; asm("ex2.approx.ftz.f32 %0, %1;" : "=f"(y) : "f"(x)); return y;
}
__device__ __forceinline__ float lg2f(float x){
    float y; asm("lg2.approx.ftz.f32 %0, %1;" : "=f"(y) : "f"(x)); return y;
}
__device__ __forceinline__ void cp8(uint32_t s, const void* g){
    asm volatile("cp.async.ca.shared.global [%0], [%1], 8;" :: "r"(s), "l"(g));
}
__device__ __forceinline__ void cp_commit(){ asm volatile("cp.async.commit_group;"); }
__device__ __forceinline__ void cp_wait2(){ asm volatile("cp.async.wait_group 2;"); }
__device__ __forceinline__ void cp_wait3(){ asm volatile("cp.async.wait_group 3;"); }

__global__ __launch_bounds__(NTHREADS, 1)
void crf_fwd_kernel(const float* __restrict__ tr,
                    const int* __restrict__ tgt,
                    float* __restrict__ out)
{
    __shared__ __align__(16) float buf[STAGES][TILE_PAD];  // 48000 B
    __shared__ __align__(16) float vbuf[2][NTAGS];
    __shared__ float scalebuf[2];
    __shared__ float tsc_sh;
    __shared__ unsigned int rank_sh;
    __shared__ unsigned char tg[SEQ];

    const int tid = threadIdx.x;
    const int b   = blockIdx.x;
    const float* trb = tr + (size_t)b * SEQ * NTRANS;

    // ---- targets ----
    if (tid < SEQ){
        int v = tgt[(size_t)b * SEQ + tid];
        tg[tid] = (unsigned char)(((unsigned)v < NTAGS) ? v : 0);
    }
    if (tid == 0) tsc_sh = 0.f;
    __syncthreads();

    // ---- target_score: all 512 gathers in the prologue, off the recurrence ----
    {
        float acc = 0.f;
        if (tid < SEQ){
            int pr = (tid == 0) ? START_TAG : (int)tg[tid-1];
            int cu = (int)tg[tid];
            acc = __ldg(trb + (size_t)tid * NTRANS + pr * NTAGS + cu);
        }
        #pragma unroll
        for (int m = 16; m > 0; m >>= 1) acc += __shfl_xor_sync(0xffffffffu, acc, m);
        if ((tid & 31) == 0) atomicAdd(&tsc_sh, acc);
    }

    const int w   = tid >> 5;
    const int l   = tid & 31;
    const int col = (w << 2) + (l & 3);   // column 0..47
    const int q   = l >> 2;               // rows 6q..6q+5
    const int r0  = q * 6;

    // 8B cp.async chunk coords (3 chunks/thread, 1152 per tile)
    const int cA = tid, cB = tid + NTHREADS, cC = tid + 2*NTHREADS;
    const uint32_t smA = (uint32_t)((cA/24)*(RST*4) + (cA%24)*8);
    const uint32_t smB = (uint32_t)((cB/24)*(RST*4) + (cB%24)*8);
    const uint32_t smC = (uint32_t)((cC/24)*(RST*4) + (cC%24)*8);
    const int gmA = (cA/24)*NTAGS + (cA%24)*2;
    const int gmB = (cB/24)*NTAGS + (cB%24)*2;
    const int gmC = (cC/24)*NTAGS + (cC%24)*2;
    const uint32_t sbase = (uint32_t)__cvta_generic_to_shared(&buf[0][0]);

    auto prefetch = [&](int tile_idx, int stg){
        uint32_t sb = sbase + (uint32_t)stg * (TILE_PAD*4);
        const float* gb = trb + (size_t)tile_idx * NTRANS;
        cp8(sb + smA, gb + gmA);
        cp8(sb + smB, gb + gmB);
        cp8(sb + smC, gb + gmC);
    };

    prefetch(0,0); cp_commit();
    prefetch(1,1); cp_commit();
    prefetch(2,2); cp_commit();
    prefetch(3,3); cp_commit();
    prefetch(4,4); cp_commit();

    cp_wait3();            // tiles 0,1 complete
    __syncthreads();

    // ---- init (t = 0) ----
    const float* b0 = &buf[0][0];
    const int P0 = __float2int_rn(b0[START_TAG*RST] * LOG2E_F);
    float v0 = ex2f(fmaf(b0[START_TAG*RST + col], LOG2E_F, (float)(-P0)));
    if (q == 0) vbuf[0][col] = v0;

    int Ksum = 0, kcur = 0;   // tid 4 only
    if (tid == 4){
        int e = (__float_as_int(v0) >> 23) & 255;   // v0 here is col 0
        kcur = e - 127;
        scalebuf[1] = __int_as_float((127 - kcur) << 23);
    }

    // Etr for step 1 from tile 1
    float E0,E1,E2,E3,E4,E5;
    {
        const float* tn = &buf[1][0];
        E0 = ex2f(tn[(r0  )*RST + col] * LOG2E_F);
        E1 = ex2f(tn[(r0+1)*RST + col] * LOG2E_F);
        E2 = ex2f(tn[(r0+2)*RST + col] * LOG2E_F);
        E3 = ex2f(tn[(r0+3)*RST + col] * LOG2E_F);
        E4 = ex2f(tn[(r0+4)*RST + col] * LOG2E_F);
        E5 = ex2f(tn[(r0+5)*RST + col] * LOG2E_F);
    }

    int st = 1;                                  // stage holding tile t
    for (int t = 1; t < SEQ; ++t){
        cp_wait2();        // tiles <= t+1 complete
        __syncthreads();   // vbuf/scalebuf of t-1 visible; stage (t-1)%5 free

        const int stp = (st == 0) ? 4 : st - 1;
        const int stn = (st == 4) ? 0 : st + 1;
        if (t + 4 < SEQ) prefetch(t + 4, stp);
        cp_commit();       // uniform group count

        const float  sc = scalebuf[t & 1];
        const float* vp = &vbuf[(t-1) & 1][0];
        const float2* vp2 = (const float2*)vp;
        float2 va = vp2[3*q], vb = vp2[3*q+1], vc = vp2[3*q+2];

        // off-path: Etr for step t+1 from tile t+1 (stale data at t=SEQ-1, unused)
        float F0,F1,F2,F3,F4,F5;
        {
            const float* tn = &buf[stn][0];
            F0 = ex2f(tn[(r0  )*RST + col] * LOG2E_F);
            F1 = ex2f(tn[(r0+1)*RST + col] * LOG2E_F);
            F2 = ex2f(tn[(r0+2)*RST + col] * LOG2E_F);
            F3 = ex2f(tn[(r0+3)*RST + col] * LOG2E_F);
            F4 = ex2f(tn[(r0+4)*RST + col] * LOG2E_F);
            F5 = ex2f(tn[(r0+5)*RST + col] * LOG2E_F);
        }

        // critical chain (E regs from previous iter)
        float s01 = fmaf(E1, va.y, E0 * va.x);
        float s23 = fmaf(E3, vb.y, E2 * vb.x);
        float s45 = fmaf(E5, vc.y, E4 * vc.x);
        float s = (s01 + s23) + s45;
        s += __shfl_xor_sync(0xffffffffu, s, 4);
        s += __shfl_xor_sync(0xffffffffu, s, 8);
        s += __shfl_xor_sync(0xffffffffu, s, 16);
        float v = s * sc;
        if (q == 0) vbuf[t & 1][col] = v;

        if (tid == 4){
            Ksum += kcur;
            float w0 = vp[0];                     // 2-step-stale scale source
            int e = (__float_as_int(w0) >> 23) & 255;
            kcur = e - 127;
            scalebuf[(t+1) & 1] = __int_as_float((127 - e + 127) << 23);
        }

        E0=F0; E1=F1; E2=F2; E3=F3; E4=F4; E5=F5;
        st = stn;
    }

    __syncthreads();
    // ---- per-block result + threadfence reduction (single-kernel finalize) ----
    if (tid == 4){
        float vf = vbuf[(SEQ-1) & 1][END_TAG];
        int   eu = ((__float_as_int(vf) >> 23) & 255) - 127;
        float mu = __int_as_float((__float_as_int(vf) & 0x807FFFFF) | 0x3F800000);
        double log2u = (double)(eu + P0 + Ksum) + (double)lg2f(mu);
        g_part[b] = (float)(LN2_D * log2u - (double)tsc_sh);
        __threadfence();
        rank_sh = atomicAdd(&g_done, 1u);
    }
    __syncthreads();

    if (rank_sh == BSZ - 1){                      // last block finalizes
        if (tid < 32){
            double vs = (double)__ldcg(&g_part[tid]) + (double)__ldcg(&g_part[tid + 32]);
            #pragma unroll
            for (int m = 16; m > 0; m >>= 1)
                vs += __shfl_xor_sync(0xffffffffu, vs, m);
            if (tid == 0){
                out[0] = (float)(vs * (1.0 / (double)BSZ));
                atomicExch(&g_done, 0u);          // reset for next graph replay
            }
        }
    }
}

extern "C" void kernel_launch(void* const* d_in, const int* in_sizes, int n_in,
                              void* d_out, int out_size)
{
    const float* tr  = (const float*)d_in[0];
    const int*   tgt = (const int*)d_in[1];
    float*       out = (float*)d_out;

    crf_fwd_kernel<<<BSZ, NTHREADS>>>(tr, tgt, out);
}